// round 8
// baseline (speedup 1.0000x reference)
#include <cuda_runtime.h>
#include <cuda_fp16.h>
#include <cstdint>

// ---------------------------------------------------------------------------
// MultiAttnLayer, sm_103 baseline-ISA path. Round 8: GEMM mainloop uses
// fp16-accumulate HMMA (testing the f32-acc-half-rate hypothesis), promoted
// to fp32 accumulators once per BK=64 k-iteration. Tile config = R6 best
// (128x128, 4 warps, 2 CTA/SM). Attention/LN unchanged.
// ---------------------------------------------------------------------------

constexpr int BB   = 4;
constexpr int SEQ  = 8192;
constexpr int DM   = 1024;
constexpr int NH   = 16;
constexpr int HD   = 64;
constexpr int WIN  = 128;
constexpr int NWIN = SEQ / WIN;
constexpr int FF   = 4096;
constexpr int T    = BB * SEQ;
constexpr float LN_EPS = 1e-5f;

// Scratch (device globals: allocation-free).
__device__ __half g_src_h[(size_t)T * DM];
__device__ __half g_win_h[3 * DM * DM];
__device__ __half g_wout_h[DM * DM];
__device__ __half g_w1_h[FF * DM];
__device__ __half g_w2_h[DM * FF];
__device__ __half g_qkv_h[(size_t)T * 3 * DM];
__device__ __half g_ctx_h[(size_t)T * DM];
__device__ __half g_h16[(size_t)T * DM];
__device__ __half g_ff_h[(size_t)T * FF];
__device__ float  g_h32[(size_t)T * DM];
__device__ float  g_x32[(size_t)T * DM];

// ========================= helpers =========================================
__device__ __forceinline__ uint32_t smem_u32(const void* p) {
    uint32_t a;
    asm("{ .reg .u64 t; cvta.to.shared.u64 t, %1; cvt.u32.u64 %0, t; }" : "=r"(a) : "l"(p));
    return a;
}
__device__ __forceinline__ void cp_async16(uint32_t dst, const void* src) {
    asm volatile("cp.async.cg.shared.global [%0], [%1], 16;" :: "r"(dst), "l"(src));
}
__device__ __forceinline__ void cp_commit() { asm volatile("cp.async.commit_group;"); }
template <int N> __device__ __forceinline__ void cp_wait() {
    asm volatile("cp.async.wait_group %0;" :: "n"(N));
}
#define LDSM_X4(r0, r1, r2, r3, addr)                                          \
    asm volatile("ldmatrix.sync.aligned.m8n8.x4.shared.b16 {%0,%1,%2,%3}, [%4];" \
        : "=r"(r0), "=r"(r1), "=r"(r2), "=r"(r3) : "r"(addr))
#define LDSM_X4_T(r0, r1, r2, r3, addr)                                        \
    asm volatile("ldmatrix.sync.aligned.m8n8.x4.trans.shared.b16 {%0,%1,%2,%3}, [%4];" \
        : "=r"(r0), "=r"(r1), "=r"(r2), "=r"(r3) : "r"(addr))

// f32-accumulate MMA (used by attention).
__device__ __forceinline__ void mma_f16(float c[4], const uint32_t a[4],
                                        uint32_t b0, uint32_t b1) {
    asm volatile(
        "mma.sync.aligned.m16n8k16.row.col.f32.f16.f16.f32 "
        "{%0,%1,%2,%3}, {%4,%5,%6,%7}, {%8,%9}, {%0,%1,%2,%3};\n"
        : "+f"(c[0]), "+f"(c[1]), "+f"(c[2]), "+f"(c[3])
        : "r"(a[0]), "r"(a[1]), "r"(a[2]), "r"(a[3]), "r"(b0), "r"(b1));
}

// f16-accumulate MMA: first (C = 0) and chained variants.
__device__ __forceinline__ void mma_h16_first(uint32_t c[2], const uint32_t a[4],
                                              uint32_t b0, uint32_t b1) {
    asm volatile(
        "mma.sync.aligned.m16n8k16.row.col.f16.f16.f16.f16 "
        "{%0,%1}, {%2,%3,%4,%5}, {%6,%7}, {%8,%9};\n"
        : "=r"(c[0]), "=r"(c[1])
        : "r"(a[0]), "r"(a[1]), "r"(a[2]), "r"(a[3]), "r"(b0), "r"(b1),
          "r"(0u), "r"(0u));
}
__device__ __forceinline__ void mma_h16_acc(uint32_t c[2], const uint32_t a[4],
                                            uint32_t b0, uint32_t b1) {
    asm volatile(
        "mma.sync.aligned.m16n8k16.row.col.f16.f16.f16.f16 "
        "{%0,%1}, {%2,%3,%4,%5}, {%6,%7}, {%0,%1};\n"
        : "+r"(c[0]), "+r"(c[1])
        : "r"(a[0]), "r"(a[1]), "r"(a[2]), "r"(a[3]), "r"(b0), "r"(b1));
}

// ========================= fp16 GEMM =======================================
// C[M,N] = A[M,K] @ B[N,K]^T + bias[N] (+ residual).  A,B fp16.
// Inner product: fp16 accumulate within each BK=64 chunk (4 chained HMMAs),
// promoted to fp32 register accumulators per k-iteration.
// Tile 128x128, BK=64, 128 threads = 4 warps (2m x 2n, warp tile 64x64),
// 3-stage cp.async, 2 CTAs/SM.
constexpr int BM = 128, BN = 128, BK = 64, STAGES = 3;
constexpr int AROW = 144;
constexpr int A_ST = BM * AROW;           // 18432
constexpr int B_ST = BN * AROW;           // 18432
constexpr int ST   = A_ST + B_ST;         // 36864
constexpr int GEMM_SMEM = STAGES * ST;    // 110592

template <int OUT_HALF, int RELU, int RES, int KV>
__global__ __launch_bounds__(128, 2)
void gemm_h(const __half* __restrict__ A, const __half* __restrict__ B,
            const float* __restrict__ bias, const float* __restrict__ Res,
            void* __restrict__ Cout, int M, int N)
{
    extern __shared__ char smraw[];
    const uint32_t sb = smem_u32(smraw);

    const int tid  = threadIdx.x;
    const int wid  = tid >> 5;
    const int lane = tid & 31;
    const int wm   = wid >> 1;           // 0..1
    const int wn   = wid & 1;            // 0..1
    const int bm   = blockIdx.y * BM;
    const int bn   = blockIdx.x * BN;
    constexpr int K = KV;

    float acc[4][8][4];
#pragma unroll
    for (int i = 0; i < 4; i++)
#pragma unroll
        for (int j = 0; j < 8; j++)
#pragma unroll
            for (int l = 0; l < 4; l++) acc[i][j][l] = 0.f;

    auto load_stage = [&](int s, int k0) {
        const uint32_t ab = sb + s * ST;
#pragma unroll
        for (int i = 0; i < 8; i++) {            // A: 128 rows x 8 chunks(16B)
            int id = tid + i * 128;
            int r  = id >> 3;
            int c  = id & 7;
            cp_async16(ab + r * AROW + c * 16, A + (size_t)(bm + r) * K + k0 + c * 8);
        }
        const uint32_t bb = ab + A_ST;
#pragma unroll
        for (int i = 0; i < 8; i++) {            // B: 128 rows x 8 chunks
            int id = tid + i * 128;
            int r  = id >> 3;
            int c  = id & 7;
            cp_async16(bb + r * AROW + c * 16, B + (size_t)(bn + r) * K + k0 + c * 8);
        }
    };

    constexpr int NK = K / BK;
#pragma unroll
    for (int s = 0; s < STAGES - 1; s++) { load_stage(s, s * BK); cp_commit(); }

    const uint32_t a_lane = (uint32_t)((lane & 15) * AROW + (lane >> 4) * 16);
    const uint32_t b_lane = (uint32_t)(((lane & 7) + ((lane >> 4) & 1) * 8) * AROW +
                                       ((lane >> 3) & 1) * 16);

    for (int k = 0; k < NK; k++) {
        cp_wait<STAGES - 2>();
        __syncthreads();
        if (k + STAGES - 1 < NK) load_stage((k + STAGES - 1) % STAGES, (k + STAGES - 1) * BK);
        cp_commit();

        const uint32_t as = sb + (k % STAGES) * ST;
        const uint32_t a_base = as + wm * 64 * AROW + a_lane;
        const uint32_t b_base = as + A_ST + wn * 64 * AROW + b_lane;

        uint32_t hC[4][8][2];   // fp16x2 chunk accumulators (live this k-iter)

#pragma unroll
        for (int ks = 0; ks < 4; ks++) {
            uint32_t a_f[4][4];
#pragma unroll
            for (int im = 0; im < 4; im++)
                LDSM_X4(a_f[im][0], a_f[im][1], a_f[im][2], a_f[im][3],
                        a_base + im * 16 * AROW + ks * 32);
            uint32_t b_f[8][2];
#pragma unroll
            for (int p = 0; p < 4; p++) {
                uint32_t r0, r1, r2, r3;
                LDSM_X4(r0, r1, r2, r3, b_base + p * 16 * AROW + ks * 32);
                b_f[2 * p][0] = r0; b_f[2 * p][1] = r1;
                b_f[2 * p + 1][0] = r2; b_f[2 * p + 1][1] = r3;
            }
#pragma unroll
            for (int im = 0; im < 4; im++)
#pragma unroll
                for (int n = 0; n < 8; n++) {
                    if (ks == 0)
                        mma_h16_first(hC[im][n], a_f[im], b_f[n][0], b_f[n][1]);
                    else
                        mma_h16_acc(hC[im][n], a_f[im], b_f[n][0], b_f[n][1]);
                }
        }

        // promote chunk -> fp32 accumulators
#pragma unroll
        for (int im = 0; im < 4; im++)
#pragma unroll
            for (int n = 0; n < 8; n++) {
                __half2 h0 = *reinterpret_cast<__half2*>(&hC[im][n][0]);
                __half2 h1 = *reinterpret_cast<__half2*>(&hC[im][n][1]);
                float2 f0 = __half22float2(h0);
                float2 f1 = __half22float2(h1);
                acc[im][n][0] += f0.x; acc[im][n][1] += f0.y;
                acc[im][n][2] += f1.x; acc[im][n][3] += f1.y;
            }
    }

    // Epilogue
#pragma unroll
    for (int im = 0; im < 4; im++) {
        const int row = bm + wm * 64 + im * 16 + (lane >> 2);
#pragma unroll
        for (int n = 0; n < 8; n++) {
            const int col = bn + wn * 64 + n * 8 + (lane & 3) * 2;
            const float2 bv = *(const float2*)(bias + col);
            float v00 = acc[im][n][0] + bv.x, v01 = acc[im][n][1] + bv.y;
            float v10 = acc[im][n][2] + bv.x, v11 = acc[im][n][3] + bv.y;
            if (RES) {
                const float2 r0 = *(const float2*)(Res + (size_t)row * N + col);
                const float2 r1 = *(const float2*)(Res + (size_t)(row + 8) * N + col);
                v00 += r0.x; v01 += r0.y;
                v10 += r1.x; v11 += r1.y;
            }
            if (RELU) {
                v00 = fmaxf(v00, 0.f); v01 = fmaxf(v01, 0.f);
                v10 = fmaxf(v10, 0.f); v11 = fmaxf(v11, 0.f);
            }
            if (OUT_HALF) {
                __half2* C = (__half2*)Cout;
                C[((size_t)row * N + col) >> 1]       = __floats2half2_rn(v00, v01);
                C[((size_t)(row + 8) * N + col) >> 1] = __floats2half2_rn(v10, v11);
            } else {
                float* C = (float*)Cout;
                *(float2*)(C + (size_t)row * N + col)       = make_float2(v00, v01);
                *(float2*)(C + (size_t)(row + 8) * N + col) = make_float2(v10, v11);
            }
        }
    }
}

// ===================== window-local attention (fp16) =======================
constexpr int QKV_B  = 128 * 144;
constexpr int P_ROWB = 272;
constexpr int OFF_P  = 3 * QKV_B;
constexpr int ATTN_SMEM = OFF_P + 128 * P_ROWB;   // 90112

__global__ __launch_bounds__(256, 2)
void attn_h()
{
    extern __shared__ char smraw[];
    const uint32_t sb = smem_u32(smraw);
    const uint32_t qh = sb;
    const uint32_t kh = sb + QKV_B;
    const uint32_t vh = sb + 2 * QKV_B;

    const int h  = blockIdx.x;
    const int w  = blockIdx.y;
    const int b  = blockIdx.z;
    const int t0 = b * SEQ + w * WIN;

    const int tid  = threadIdx.x;
    const int wid  = tid >> 5;
    const int lane = tid & 31;
    const int gid  = lane >> 2;
    const int tig  = lane & 3;

#pragma unroll
    for (int i = 0; i < 4; i++) {
        int id = tid + i * 256;
        int r  = id >> 3;
        int c  = id & 7;
        const __half* base = g_qkv_h + (size_t)(t0 + r) * (3 * DM) + h * HD + c * 8;
        uint32_t doff = r * 144 + c * 16;
        cp_async16(qh + doff, base);
        cp_async16(kh + doff, base + DM);
        cp_async16(vh + doff, base + 2 * DM);
    }
    cp_commit();
    cp_wait<0>();
    __syncthreads();

    const int m0 = wid * 16;

    // ---- scores = Q @ K^T ----
    float sc[16][4];
#pragma unroll
    for (int n = 0; n < 16; n++)
#pragma unroll
        for (int l = 0; l < 4; l++) sc[n][l] = 0.f;

    const uint32_t a_base = qh + (m0 + (lane & 15)) * 144 + (lane >> 4) * 16;
    const uint32_t k_base = kh + ((lane & 7) + ((lane >> 4) & 1) * 8) * 144 +
                            ((lane >> 3) & 1) * 16;
#pragma unroll
    for (int ks = 0; ks < 4; ks++) {
        uint32_t a[4];
        LDSM_X4(a[0], a[1], a[2], a[3], a_base + ks * 32);
#pragma unroll
        for (int p = 0; p < 8; p++) {
            uint32_t r0, r1, r2, r3;
            LDSM_X4(r0, r1, r2, r3, k_base + p * 16 * 144 + ks * 32);
            mma_f16(sc[2 * p], a, r0, r1);
            mma_f16(sc[2 * p + 1], a, r2, r3);
        }
    }

    // ---- softmax in registers ----
    const float scale = 0.125f;
    float mA = -1e30f, mB = -1e30f;
#pragma unroll
    for (int n = 0; n < 16; n++) {
#pragma unroll
        for (int l = 0; l < 4; l++) sc[n][l] *= scale;
        mA = fmaxf(mA, fmaxf(sc[n][0], sc[n][1]));
        mB = fmaxf(mB, fmaxf(sc[n][2], sc[n][3]));
    }
    mA = fmaxf(mA, __shfl_xor_sync(0xffffffffu, mA, 1));
    mA = fmaxf(mA, __shfl_xor_sync(0xffffffffu, mA, 2));
    mB = fmaxf(mB, __shfl_xor_sync(0xffffffffu, mB, 1));
    mB = fmaxf(mB, __shfl_xor_sync(0xffffffffu, mB, 2));

    float sA = 0.f, sB = 0.f;
#pragma unroll
    for (int n = 0; n < 16; n++) {
        sc[n][0] = __expf(sc[n][0] - mA);
        sc[n][1] = __expf(sc[n][1] - mA);
        sc[n][2] = __expf(sc[n][2] - mB);
        sc[n][3] = __expf(sc[n][3] - mB);
        sA += sc[n][0] + sc[n][1];
        sB += sc[n][2] + sc[n][3];
    }
    sA += __shfl_xor_sync(0xffffffffu, sA, 1);
    sA += __shfl_xor_sync(0xffffffffu, sA, 2);
    sB += __shfl_xor_sync(0xffffffffu, sB, 1);
    sB += __shfl_xor_sync(0xffffffffu, sB, 2);
    const float invA = 1.f / sA, invB = 1.f / sB;

    {
        const int rA = m0 + gid;
        __half2* pA = (__half2*)(smraw + OFF_P + rA * P_ROWB);
        __half2* pB = (__half2*)(smraw + OFF_P + (rA + 8) * P_ROWB);
#pragma unroll
        for (int n = 0; n < 16; n++) {
            const int c2 = (n * 8 + tig * 2) >> 1;
            pA[c2] = __floats2half2_rn(sc[n][0] * invA, sc[n][1] * invA);
            pB[c2] = __floats2half2_rn(sc[n][2] * invB, sc[n][3] * invB);
        }
    }
    __syncthreads();

    // ---- ctx = P @ V ----
    float o[8][4];
#pragma unroll
    for (int n = 0; n < 8; n++)
#pragma unroll
        for (int l = 0; l < 4; l++) o[n][l] = 0.f;

    const uint32_t p_base = sb + OFF_P + (m0 + (lane & 15)) * P_ROWB + (lane >> 4) * 16;
    const uint32_t v_base = vh + ((lane & 7) + ((lane >> 3) & 1) * 8) * 144 +
                            (lane >> 4) * 16;
#pragma unroll
    for (int ks = 0; ks < 8; ks++) {
        uint32_t a[4];
        LDSM_X4(a[0], a[1], a[2], a[3], p_base + ks * 32);
#pragma unroll
        for (int p = 0; p < 4; p++) {
            uint32_t r0, r1, r2, r3;
            LDSM_X4_T(r0, r1, r2, r3, v_base + ks * 16 * 144 + p * 32);
            mma_f16(o[2 * p], a, r0, r1);
            mma_f16(o[2 * p + 1], a, r2, r3);
        }
    }

    {
        const int r = m0 + gid;
#pragma unroll
        for (int n = 0; n < 8; n++) {
            const int c = h * HD + n * 8 + tig * 2;
            __half2* o0 = (__half2*)(g_ctx_h + (size_t)(t0 + r) * DM + c);
            __half2* o1 = (__half2*)(g_ctx_h + (size_t)(t0 + r + 8) * DM + c);
            *o0 = __floats2half2_rn(o[n][0], o[n][1]);
            *o1 = __floats2half2_rn(o[n][2], o[n][3]);
        }
    }
}

// ============================ LayerNorm ====================================
__global__ __launch_bounds__(256)
void ln_kernel(const float* __restrict__ X,
               const float* __restrict__ gam, const float* __restrict__ bet,
               float* __restrict__ out, __half* __restrict__ out16)
{
    const int t    = blockIdx.x;
    const int tid  = threadIdx.x;
    const int lane = tid & 31;
    const int wid  = tid >> 5;

    const size_t base = (size_t)t * DM + tid * 4;
    float4 a = *(const float4*)(X + base);
    float x0 = a.x, x1 = a.y, x2 = a.z, x3 = a.w;

    float s = x0 + x1 + x2 + x3;
    float q = x0 * x0 + x1 * x1 + x2 * x2 + x3 * x3;
#pragma unroll
    for (int o = 16; o > 0; o >>= 1) {
        s += __shfl_xor_sync(0xffffffffu, s, o);
        q += __shfl_xor_sync(0xffffffffu, q, o);
    }
    __shared__ float rs[8], rq[8];
    if (lane == 0) { rs[wid] = s; rq[wid] = q; }
    __syncthreads();
    if (wid == 0) {
        s = (lane < 8) ? rs[lane] : 0.f;
        q = (lane < 8) ? rq[lane] : 0.f;
#pragma unroll
        for (int o = 4; o > 0; o >>= 1) {
            s += __shfl_xor_sync(0xffffffffu, s, o);
            q += __shfl_xor_sync(0xffffffffu, q, o);
        }
        if (lane == 0) { rs[0] = s; rq[0] = q; }
    }
    __syncthreads();
    const float mu   = rs[0] * (1.f / DM);
    const float var  = rq[0] * (1.f / DM) - mu * mu;
    const float rstd = rsqrtf(var + LN_EPS);

    float4 gv = *(const float4*)(gam + tid * 4);
    float4 bv = *(const float4*)(bet + tid * 4);
    float4 r;
    r.x = (x0 - mu) * rstd * gv.x + bv.x;
    r.y = (x1 - mu) * rstd * gv.y + bv.y;
    r.z = (x2 - mu) * rstd * gv.z + bv.z;
    r.w = (x3 - mu) * rstd * gv.w + bv.w;
    *(float4*)(out + base) = r;
    if (out16) {
        *(__half2*)(out16 + base)     = __floats2half2_rn(r.x, r.y);
        *(__half2*)(out16 + base + 2) = __floats2half2_rn(r.z, r.w);
    }
}

// ================= fused fp32 -> fp16 convert (all 5 arrays) ===============
constexpr int N4_SRC = T * DM / 4;
constexpr int N4_WIN = 3 * DM * DM / 4;
constexpr int N4_WO  = DM * DM / 4;
constexpr int N4_W1  = FF * DM / 4;
constexpr int N4_W2  = DM * FF / 4;
constexpr int N4_ALL = N4_SRC + N4_WIN + N4_WO + N4_W1 + N4_W2;

__global__ __launch_bounds__(256)
void cvt_all(const float* __restrict__ s0, const float* __restrict__ s1,
             const float* __restrict__ s2, const float* __restrict__ s3,
             const float* __restrict__ s4,
             __half* __restrict__ d0, __half* __restrict__ d1,
             __half* __restrict__ d2, __half* __restrict__ d3,
             __half* __restrict__ d4)
{
    int i = blockIdx.x * 256 + threadIdx.x;
    const float* in;
    __half* out;
    if (i < N4_SRC)                       { in = s0; out = d0; }
    else if ((i -= N4_SRC) < N4_WIN)      { in = s1; out = d1; }
    else if ((i -= N4_WIN) < N4_WO)       { in = s2; out = d2; }
    else if ((i -= N4_WO)  < N4_W1)       { in = s3; out = d3; }
    else if ((i -= N4_W1)  < N4_W2)       { in = s4; out = d4; }
    else return;
    float4 v = *(const float4*)(in + (size_t)i * 4);
    *(__half2*)(out + (size_t)i * 4)     = __floats2half2_rn(v.x, v.y);
    *(__half2*)(out + (size_t)i * 4 + 2) = __floats2half2_rn(v.z, v.w);
}

// ---------------------------------------------------------------------------
extern "C" void kernel_launch(void* const* d_in, const int* in_sizes, int n_in,
                              void* d_out, int out_size)
{
    const float* src   = (const float*)d_in[0];
    const float* in_w  = (const float*)d_in[1];
    const float* in_b  = (const float*)d_in[2];
    const float* ow    = (const float*)d_in[3];
    const float* ob    = (const float*)d_in[4];
    const float* w1    = (const float*)d_in[5];
    const float* b1    = (const float*)d_in[6];
    const float* w2    = (const float*)d_in[7];
    const float* b2    = (const float*)d_in[8];
    const float* ln1g  = (const float*)d_in[9];
    const float* ln1b  = (const float*)d_in[10];
    const float* ln2g  = (const float*)d_in[11];
    const float* ln2b  = (const float*)d_in[12];
    float* out = (float*)d_out;

    __half *src_h, *win_h, *wout_h, *w1_h, *w2_h, *qkv_h, *ctx_h, *h16, *ff_h;
    float *h32, *x32;
    cudaGetSymbolAddress((void**)&src_h,  g_src_h);
    cudaGetSymbolAddress((void**)&win_h,  g_win_h);
    cudaGetSymbolAddress((void**)&wout_h, g_wout_h);
    cudaGetSymbolAddress((void**)&w1_h,   g_w1_h);
    cudaGetSymbolAddress((void**)&w2_h,   g_w2_h);
    cudaGetSymbolAddress((void**)&qkv_h,  g_qkv_h);
    cudaGetSymbolAddress((void**)&ctx_h,  g_ctx_h);
    cudaGetSymbolAddress((void**)&h16,    g_h16);
    cudaGetSymbolAddress((void**)&ff_h,   g_ff_h);
    cudaGetSymbolAddress((void**)&h32,    g_h32);
    cudaGetSymbolAddress((void**)&x32,    g_x32);

    cudaFuncSetAttribute(gemm_h<1, 0, 0, DM>, cudaFuncAttributeMaxDynamicSharedMemorySize, GEMM_SMEM);
    cudaFuncSetAttribute(gemm_h<0, 0, 1, DM>, cudaFuncAttributeMaxDynamicSharedMemorySize, GEMM_SMEM);
    cudaFuncSetAttribute(gemm_h<1, 1, 0, DM>, cudaFuncAttributeMaxDynamicSharedMemorySize, GEMM_SMEM);
    cudaFuncSetAttribute(gemm_h<0, 0, 1, FF>, cudaFuncAttributeMaxDynamicSharedMemorySize, GEMM_SMEM);
    cudaFuncSetAttribute(attn_h, cudaFuncAttributeMaxDynamicSharedMemorySize, ATTN_SMEM);

    // 0. fused convert of src + all weights to fp16 (one launch)
    cvt_all<<<(N4_ALL + 255) / 256, 256>>>(src, in_w, ow, w1, w2,
                                           src_h, win_h, wout_h, w1_h, w2_h);
    // 1. qkv = src @ in_w^T + b (fp16 out)
    gemm_h<1, 0, 0, DM><<<dim3(3 * DM / BN, T / BM), 128, GEMM_SMEM>>>(
        src_h, win_h, in_b, nullptr, qkv_h, T, 3 * DM);
    // 2. window-local attention -> ctx fp16
    attn_h<<<dim3(NH, NWIN, BB), 256, ATTN_SMEM>>>();
    // 3. x = ctx @ ow^T + ob + src (fp32 out, residual fused)
    gemm_h<0, 0, 1, DM><<<dim3(DM / BN, T / BM), 128, GEMM_SMEM>>>(
        ctx_h, wout_h, ob, src, x32, T, DM);
    // 4. h = LN(x)
    ln_kernel<<<T, 256>>>(x32, ln1g, ln1b, h32, h16);
    // 5. ff = relu(h @ w1^T + b1) (fp16 out)
    gemm_h<1, 1, 0, DM><<<dim3(FF / BN, T / BM), 128, GEMM_SMEM>>>(
        h16, w1_h, b1, nullptr, ff_h, T, FF);
    // 6. x = ff @ w2^T + b2 + h (fp32 out, residual fused)
    gemm_h<0, 0, 1, FF><<<dim3(DM / BN, T / BM), 128, GEMM_SMEM>>>(
        ff_h, w2_h, b2, h32, x32, T, DM);
    // 7. out = LN(x)
    ln_kernel<<<T, 256>>>(x32, ln2g, ln2b, out, nullptr);
}

// round 9
// speedup vs baseline: 1.0912x; 1.0912x over previous
#include <cuda_runtime.h>
#include <cuda_fp16.h>
#include <cstdint>

// ---------------------------------------------------------------------------
// MultiAttnLayer, sm_103 baseline-ISA path. Round 9: R6 GEMM core (best:
// 128x128 tile, 4 warps, 2 CTA/SM, reg double-buffered frags) + full fp16
// inter-kernel dataflow: fp16 residuals, fp16 GEMM outputs, LN reads fp16.
// ---------------------------------------------------------------------------

constexpr int BB   = 4;
constexpr int SEQ  = 8192;
constexpr int DM   = 1024;
constexpr int NH   = 16;
constexpr int HD   = 64;
constexpr int WIN  = 128;
constexpr int NWIN = SEQ / WIN;
constexpr int FF   = 4096;
constexpr int T    = BB * SEQ;
constexpr float LN_EPS = 1e-5f;

// Scratch (device globals: allocation-free).
__device__ __half g_src_h[(size_t)T * DM];
__device__ __half g_win_h[3 * DM * DM];
__device__ __half g_wout_h[DM * DM];
__device__ __half g_w1_h[FF * DM];
__device__ __half g_w2_h[DM * FF];
__device__ __half g_qkv_h[(size_t)T * 3 * DM];
__device__ __half g_ctx_h[(size_t)T * DM];
__device__ __half g_h16[(size_t)T * DM];
__device__ __half g_ff_h[(size_t)T * FF];
__device__ __half g_x16[(size_t)T * DM];

// ========================= helpers =========================================
__device__ __forceinline__ uint32_t smem_u32(const void* p) {
    uint32_t a;
    asm("{ .reg .u64 t; cvta.to.shared.u64 t, %1; cvt.u32.u64 %0, t; }" : "=r"(a) : "l"(p));
    return a;
}
__device__ __forceinline__ void cp_async16(uint32_t dst, const void* src) {
    asm volatile("cp.async.cg.shared.global [%0], [%1], 16;" :: "r"(dst), "l"(src));
}
__device__ __forceinline__ void cp_commit() { asm volatile("cp.async.commit_group;"); }
template <int N> __device__ __forceinline__ void cp_wait() {
    asm volatile("cp.async.wait_group %0;" :: "n"(N));
}
#define LDSM_X4(r0, r1, r2, r3, addr)                                          \
    asm volatile("ldmatrix.sync.aligned.m8n8.x4.shared.b16 {%0,%1,%2,%3}, [%4];" \
        : "=r"(r0), "=r"(r1), "=r"(r2), "=r"(r3) : "r"(addr))
#define LDSM_X4_T(r0, r1, r2, r3, addr)                                        \
    asm volatile("ldmatrix.sync.aligned.m8n8.x4.trans.shared.b16 {%0,%1,%2,%3}, [%4];" \
        : "=r"(r0), "=r"(r1), "=r"(r2), "=r"(r3) : "r"(addr))

__device__ __forceinline__ void mma_f16(float c[4], const uint32_t a[4],
                                        uint32_t b0, uint32_t b1) {
    asm volatile(
        "mma.sync.aligned.m16n8k16.row.col.f32.f16.f16.f32 "
        "{%0,%1,%2,%3}, {%4,%5,%6,%7}, {%8,%9}, {%0,%1,%2,%3};\n"
        : "+f"(c[0]), "+f"(c[1]), "+f"(c[2]), "+f"(c[3])
        : "r"(a[0]), "r"(a[1]), "r"(a[2]), "r"(a[3]), "r"(b0), "r"(b1));
}

// ========================= fp16 GEMM =======================================
// C[M,N] = A[M,K] @ B[N,K]^T + bias[N] (+ fp16 residual).  A,B fp16; acc fp32.
// Tile 128x128, BK=64, 128 threads = 4 warps (2m x 2n, warp tile 64x64),
// 3-stage cp.async, 2 CTAs/SM, register double-buffered fragments.
constexpr int BM = 128, BN = 128, BK = 64, STAGES = 3;
constexpr int AROW = 144;                 // 64 halves + 8 pad (conflict-free LDSM)
constexpr int A_ST = BM * AROW;           // 18432
constexpr int B_ST = BN * AROW;           // 18432
constexpr int ST   = A_ST + B_ST;         // 36864
constexpr int GEMM_SMEM = STAGES * ST;    // 110592

template <int OUT_HALF, int RELU, int RES, int KV>
__global__ __launch_bounds__(128, 2)
void gemm_h(const __half* __restrict__ A, const __half* __restrict__ B,
            const float* __restrict__ bias, const __half* __restrict__ Res,
            void* __restrict__ Cout, int M, int N)
{
    extern __shared__ char smraw[];
    const uint32_t sb = smem_u32(smraw);

    const int tid  = threadIdx.x;
    const int wid  = tid >> 5;
    const int lane = tid & 31;
    const int wm   = wid >> 1;           // 0..1
    const int wn   = wid & 1;            // 0..1
    const int bm   = blockIdx.y * BM;
    const int bn   = blockIdx.x * BN;
    constexpr int K = KV;

    float acc[4][8][4];
#pragma unroll
    for (int i = 0; i < 4; i++)
#pragma unroll
        for (int j = 0; j < 8; j++)
#pragma unroll
            for (int l = 0; l < 4; l++) acc[i][j][l] = 0.f;

    auto load_stage = [&](int s, int k0) {
        const uint32_t ab = sb + s * ST;
#pragma unroll
        for (int i = 0; i < 8; i++) {
            int id = tid + i * 128;
            int r  = id >> 3;
            int c  = id & 7;
            cp_async16(ab + r * AROW + c * 16, A + (size_t)(bm + r) * K + k0 + c * 8);
        }
        const uint32_t bb = ab + A_ST;
#pragma unroll
        for (int i = 0; i < 8; i++) {
            int id = tid + i * 128;
            int r  = id >> 3;
            int c  = id & 7;
            cp_async16(bb + r * AROW + c * 16, B + (size_t)(bn + r) * K + k0 + c * 8);
        }
    };

    constexpr int NK = K / BK;
#pragma unroll
    for (int s = 0; s < STAGES - 1; s++) { load_stage(s, s * BK); cp_commit(); }

    const uint32_t a_lane = (uint32_t)((lane & 15) * AROW + (lane >> 4) * 16);
    const uint32_t b_lane = (uint32_t)(((lane & 7) + ((lane >> 4) & 1) * 8) * AROW +
                                       ((lane >> 3) & 1) * 16);

    for (int k = 0; k < NK; k++) {
        cp_wait<STAGES - 2>();
        __syncthreads();
        if (k + STAGES - 1 < NK) load_stage((k + STAGES - 1) % STAGES, (k + STAGES - 1) * BK);
        cp_commit();

        const uint32_t as = sb + (k % STAGES) * ST;
        const uint32_t a_base = as + wm * 64 * AROW + a_lane;
        const uint32_t b_base = as + A_ST + wn * 64 * AROW + b_lane;

        uint32_t a_f[2][4][4];
        uint32_t b_f[2][8][2];

        // prime ks=0 fragments
#pragma unroll
        for (int im = 0; im < 4; im++)
            LDSM_X4(a_f[0][im][0], a_f[0][im][1], a_f[0][im][2], a_f[0][im][3],
                    a_base + im * 16 * AROW);
#pragma unroll
        for (int p = 0; p < 4; p++) {
            uint32_t r0, r1, r2, r3;
            LDSM_X4(r0, r1, r2, r3, b_base + p * 16 * AROW);
            b_f[0][2 * p][0] = r0; b_f[0][2 * p][1] = r1;
            b_f[0][2 * p + 1][0] = r2; b_f[0][2 * p + 1][1] = r3;
        }

#pragma unroll
        for (int ks = 0; ks < 4; ks++) {
            const int cb = ks & 1;
            const int nb = cb ^ 1;
            if (ks < 3) {
#pragma unroll
                for (int im = 0; im < 4; im++)
                    LDSM_X4(a_f[nb][im][0], a_f[nb][im][1], a_f[nb][im][2], a_f[nb][im][3],
                            a_base + im * 16 * AROW + (ks + 1) * 32);
#pragma unroll
                for (int p = 0; p < 4; p++) {
                    uint32_t r0, r1, r2, r3;
                    LDSM_X4(r0, r1, r2, r3, b_base + p * 16 * AROW + (ks + 1) * 32);
                    b_f[nb][2 * p][0] = r0; b_f[nb][2 * p][1] = r1;
                    b_f[nb][2 * p + 1][0] = r2; b_f[nb][2 * p + 1][1] = r3;
                }
            }
#pragma unroll
            for (int im = 0; im < 4; im++)
#pragma unroll
                for (int n = 0; n < 8; n++)
                    mma_f16(acc[im][n], a_f[cb][im], b_f[cb][n][0], b_f[cb][n][1]);
        }
    }

    // Epilogue (fp16 residual, optional fp16/fp32 output)
#pragma unroll
    for (int im = 0; im < 4; im++) {
        const int row = bm + wm * 64 + im * 16 + (lane >> 2);
#pragma unroll
        for (int n = 0; n < 8; n++) {
            const int col = bn + wn * 64 + n * 8 + (lane & 3) * 2;
            const float2 bv = *(const float2*)(bias + col);
            float v00 = acc[im][n][0] + bv.x, v01 = acc[im][n][1] + bv.y;
            float v10 = acc[im][n][2] + bv.x, v11 = acc[im][n][3] + bv.y;
            if (RES) {
                const float2 r0 = __half22float2(
                    *(const __half2*)(Res + (size_t)row * N + col));
                const float2 r1 = __half22float2(
                    *(const __half2*)(Res + (size_t)(row + 8) * N + col));
                v00 += r0.x; v01 += r0.y;
                v10 += r1.x; v11 += r1.y;
            }
            if (RELU) {
                v00 = fmaxf(v00, 0.f); v01 = fmaxf(v01, 0.f);
                v10 = fmaxf(v10, 0.f); v11 = fmaxf(v11, 0.f);
            }
            if (OUT_HALF) {
                __half2* C = (__half2*)Cout;
                C[((size_t)row * N + col) >> 1]       = __floats2half2_rn(v00, v01);
                C[((size_t)(row + 8) * N + col) >> 1] = __floats2half2_rn(v10, v11);
            } else {
                float* C = (float*)Cout;
                *(float2*)(C + (size_t)row * N + col)       = make_float2(v00, v01);
                *(float2*)(C + (size_t)(row + 8) * N + col) = make_float2(v10, v11);
            }
        }
    }
}

// ===================== window-local attention (fp16) =======================
constexpr int QKV_B  = 128 * 144;
constexpr int P_ROWB = 272;
constexpr int OFF_P  = 3 * QKV_B;
constexpr int ATTN_SMEM = OFF_P + 128 * P_ROWB;   // 90112

__global__ __launch_bounds__(256, 2)
void attn_h()
{
    extern __shared__ char smraw[];
    const uint32_t sb = smem_u32(smraw);
    const uint32_t qh = sb;
    const uint32_t kh = sb + QKV_B;
    const uint32_t vh = sb + 2 * QKV_B;

    const int h  = blockIdx.x;
    const int w  = blockIdx.y;
    const int b  = blockIdx.z;
    const int t0 = b * SEQ + w * WIN;

    const int tid  = threadIdx.x;
    const int wid  = tid >> 5;
    const int lane = tid & 31;
    const int gid  = lane >> 2;
    const int tig  = lane & 3;

#pragma unroll
    for (int i = 0; i < 4; i++) {
        int id = tid + i * 256;
        int r  = id >> 3;
        int c  = id & 7;
        const __half* base = g_qkv_h + (size_t)(t0 + r) * (3 * DM) + h * HD + c * 8;
        uint32_t doff = r * 144 + c * 16;
        cp_async16(qh + doff, base);
        cp_async16(kh + doff, base + DM);
        cp_async16(vh + doff, base + 2 * DM);
    }
    cp_commit();
    cp_wait<0>();
    __syncthreads();

    const int m0 = wid * 16;

    // ---- scores = Q @ K^T ----
    float sc[16][4];
#pragma unroll
    for (int n = 0; n < 16; n++)
#pragma unroll
        for (int l = 0; l < 4; l++) sc[n][l] = 0.f;

    const uint32_t a_base = qh + (m0 + (lane & 15)) * 144 + (lane >> 4) * 16;
    const uint32_t k_base = kh + ((lane & 7) + ((lane >> 4) & 1) * 8) * 144 +
                            ((lane >> 3) & 1) * 16;
#pragma unroll
    for (int ks = 0; ks < 4; ks++) {
        uint32_t a[4];
        LDSM_X4(a[0], a[1], a[2], a[3], a_base + ks * 32);
#pragma unroll
        for (int p = 0; p < 8; p++) {
            uint32_t r0, r1, r2, r3;
            LDSM_X4(r0, r1, r2, r3, k_base + p * 16 * 144 + ks * 32);
            mma_f16(sc[2 * p], a, r0, r1);
            mma_f16(sc[2 * p + 1], a, r2, r3);
        }
    }

    // ---- softmax in registers ----
    const float scale = 0.125f;
    float mA = -1e30f, mB = -1e30f;
#pragma unroll
    for (int n = 0; n < 16; n++) {
#pragma unroll
        for (int l = 0; l < 4; l++) sc[n][l] *= scale;
        mA = fmaxf(mA, fmaxf(sc[n][0], sc[n][1]));
        mB = fmaxf(mB, fmaxf(sc[n][2], sc[n][3]));
    }
    mA = fmaxf(mA, __shfl_xor_sync(0xffffffffu, mA, 1));
    mA = fmaxf(mA, __shfl_xor_sync(0xffffffffu, mA, 2));
    mB = fmaxf(mB, __shfl_xor_sync(0xffffffffu, mB, 1));
    mB = fmaxf(mB, __shfl_xor_sync(0xffffffffu, mB, 2));

    float sA = 0.f, sB = 0.f;
#pragma unroll
    for (int n = 0; n < 16; n++) {
        sc[n][0] = __expf(sc[n][0] - mA);
        sc[n][1] = __expf(sc[n][1] - mA);
        sc[n][2] = __expf(sc[n][2] - mB);
        sc[n][3] = __expf(sc[n][3] - mB);
        sA += sc[n][0] + sc[n][1];
        sB += sc[n][2] + sc[n][3];
    }
    sA += __shfl_xor_sync(0xffffffffu, sA, 1);
    sA += __shfl_xor_sync(0xffffffffu, sA, 2);
    sB += __shfl_xor_sync(0xffffffffu, sB, 1);
    sB += __shfl_xor_sync(0xffffffffu, sB, 2);
    const float invA = 1.f / sA, invB = 1.f / sB;

    {
        const int rA = m0 + gid;
        __half2* pA = (__half2*)(smraw + OFF_P + rA * P_ROWB);
        __half2* pB = (__half2*)(smraw + OFF_P + (rA + 8) * P_ROWB);
#pragma unroll
        for (int n = 0; n < 16; n++) {
            const int c2 = (n * 8 + tig * 2) >> 1;
            pA[c2] = __floats2half2_rn(sc[n][0] * invA, sc[n][1] * invA);
            pB[c2] = __floats2half2_rn(sc[n][2] * invB, sc[n][3] * invB);
        }
    }
    __syncthreads();

    // ---- ctx = P @ V ----
    float o[8][4];
#pragma unroll
    for (int n = 0; n < 8; n++)
#pragma unroll
        for (int l = 0; l < 4; l++) o[n][l] = 0.f;

    const uint32_t p_base = sb + OFF_P + (m0 + (lane & 15)) * P_ROWB + (lane >> 4) * 16;
    const uint32_t v_base = vh + ((lane & 7) + ((lane >> 3) & 1) * 8) * 144 +
                            (lane >> 4) * 16;
#pragma unroll
    for (int ks = 0; ks < 8; ks++) {
        uint32_t a[4];
        LDSM_X4(a[0], a[1], a[2], a[3], p_base + ks * 32);
#pragma unroll
        for (int p = 0; p < 4; p++) {
            uint32_t r0, r1, r2, r3;
            LDSM_X4_T(r0, r1, r2, r3, v_base + ks * 16 * 144 + p * 32);
            mma_f16(o[2 * p], a, r0, r1);
            mma_f16(o[2 * p + 1], a, r2, r3);
        }
    }

    {
        const int r = m0 + gid;
#pragma unroll
        for (int n = 0; n < 8; n++) {
            const int c = h * HD + n * 8 + tig * 2;
            __half2* o0 = (__half2*)(g_ctx_h + (size_t)(t0 + r) * DM + c);
            __half2* o1 = (__half2*)(g_ctx_h + (size_t)(t0 + r + 8) * DM + c);
            *o0 = __floats2half2_rn(o[n][0], o[n][1]);
            *o1 = __floats2half2_rn(o[n][2], o[n][3]);
        }
    }
}

// ===================== LayerNorm (fp16 in, fp32/fp16 out) ==================
__global__ __launch_bounds__(256)
void ln_h(const __half* __restrict__ X,
          const float* __restrict__ gam, const float* __restrict__ bet,
          float* __restrict__ out32, __half* __restrict__ out16)
{
    const int t    = blockIdx.x;
    const int tid  = threadIdx.x;
    const int lane = tid & 31;
    const int wid  = tid >> 5;

    const size_t base = (size_t)t * DM + tid * 4;
    float2 a0 = __half22float2(*(const __half2*)(X + base));
    float2 a1 = __half22float2(*(const __half2*)(X + base + 2));
    float x0 = a0.x, x1 = a0.y, x2 = a1.x, x3 = a1.y;

    float s = x0 + x1 + x2 + x3;
    float q = x0 * x0 + x1 * x1 + x2 * x2 + x3 * x3;
#pragma unroll
    for (int o = 16; o > 0; o >>= 1) {
        s += __shfl_xor_sync(0xffffffffu, s, o);
        q += __shfl_xor_sync(0xffffffffu, q, o);
    }
    __shared__ float rs[8], rq[8];
    if (lane == 0) { rs[wid] = s; rq[wid] = q; }
    __syncthreads();
    if (wid == 0) {
        s = (lane < 8) ? rs[lane] : 0.f;
        q = (lane < 8) ? rq[lane] : 0.f;
#pragma unroll
        for (int o = 4; o > 0; o >>= 1) {
            s += __shfl_xor_sync(0xffffffffu, s, o);
            q += __shfl_xor_sync(0xffffffffu, q, o);
        }
        if (lane == 0) { rs[0] = s; rq[0] = q; }
    }
    __syncthreads();
    const float mu   = rs[0] * (1.f / DM);
    const float var  = rq[0] * (1.f / DM) - mu * mu;
    const float rstd = rsqrtf(var + LN_EPS);

    float4 gv = *(const float4*)(gam + tid * 4);
    float4 bv = *(const float4*)(bet + tid * 4);
    float r0 = (x0 - mu) * rstd * gv.x + bv.x;
    float r1 = (x1 - mu) * rstd * gv.y + bv.y;
    float r2 = (x2 - mu) * rstd * gv.z + bv.z;
    float r3 = (x3 - mu) * rstd * gv.w + bv.w;
    if (out32) {
        float4 r;
        r.x = r0; r.y = r1; r.z = r2; r.w = r3;
        *(float4*)(out32 + base) = r;
    }
    if (out16) {
        *(__half2*)(out16 + base)     = __floats2half2_rn(r0, r1);
        *(__half2*)(out16 + base + 2) = __floats2half2_rn(r2, r3);
    }
}

// ================= fused fp32 -> fp16 convert (all 5 arrays) ===============
constexpr int N4_SRC = T * DM / 4;
constexpr int N4_WIN = 3 * DM * DM / 4;
constexpr int N4_WO  = DM * DM / 4;
constexpr int N4_W1  = FF * DM / 4;
constexpr int N4_W2  = DM * FF / 4;
constexpr int N4_ALL = N4_SRC + N4_WIN + N4_WO + N4_W1 + N4_W2;

__global__ __launch_bounds__(256)
void cvt_all(const float* __restrict__ s0, const float* __restrict__ s1,
             const float* __restrict__ s2, const float* __restrict__ s3,
             const float* __restrict__ s4,
             __half* __restrict__ d0, __half* __restrict__ d1,
             __half* __restrict__ d2, __half* __restrict__ d3,
             __half* __restrict__ d4)
{
    int i = blockIdx.x * 256 + threadIdx.x;
    const float* in;
    __half* out;
    if (i < N4_SRC)                       { in = s0; out = d0; }
    else if ((i -= N4_SRC) < N4_WIN)      { in = s1; out = d1; }
    else if ((i -= N4_WIN) < N4_WO)       { in = s2; out = d2; }
    else if ((i -= N4_WO)  < N4_W1)       { in = s3; out = d3; }
    else if ((i -= N4_W1)  < N4_W2)       { in = s4; out = d4; }
    else return;
    float4 v = *(const float4*)(in + (size_t)i * 4);
    *(__half2*)(out + (size_t)i * 4)     = __floats2half2_rn(v.x, v.y);
    *(__half2*)(out + (size_t)i * 4 + 2) = __floats2half2_rn(v.z, v.w);
}

// ---------------------------------------------------------------------------
extern "C" void kernel_launch(void* const* d_in, const int* in_sizes, int n_in,
                              void* d_out, int out_size)
{
    const float* src   = (const float*)d_in[0];
    const float* in_w  = (const float*)d_in[1];
    const float* in_b  = (const float*)d_in[2];
    const float* ow    = (const float*)d_in[3];
    const float* ob    = (const float*)d_in[4];
    const float* w1    = (const float*)d_in[5];
    const float* b1    = (const float*)d_in[6];
    const float* w2    = (const float*)d_in[7];
    const float* b2    = (const float*)d_in[8];
    const float* ln1g  = (const float*)d_in[9];
    const float* ln1b  = (const float*)d_in[10];
    const float* ln2g  = (const float*)d_in[11];
    const float* ln2b  = (const float*)d_in[12];
    float* out = (float*)d_out;

    __half *src_h, *win_h, *wout_h, *w1_h, *w2_h, *qkv_h, *ctx_h, *h16, *ff_h, *x16;
    cudaGetSymbolAddress((void**)&src_h,  g_src_h);
    cudaGetSymbolAddress((void**)&win_h,  g_win_h);
    cudaGetSymbolAddress((void**)&wout_h, g_wout_h);
    cudaGetSymbolAddress((void**)&w1_h,   g_w1_h);
    cudaGetSymbolAddress((void**)&w2_h,   g_w2_h);
    cudaGetSymbolAddress((void**)&qkv_h,  g_qkv_h);
    cudaGetSymbolAddress((void**)&ctx_h,  g_ctx_h);
    cudaGetSymbolAddress((void**)&h16,    g_h16);
    cudaGetSymbolAddress((void**)&ff_h,   g_ff_h);
    cudaGetSymbolAddress((void**)&x16,    g_x16);

    cudaFuncSetAttribute(gemm_h<1, 0, 0, DM>, cudaFuncAttributeMaxDynamicSharedMemorySize, GEMM_SMEM);
    cudaFuncSetAttribute(gemm_h<1, 0, 1, DM>, cudaFuncAttributeMaxDynamicSharedMemorySize, GEMM_SMEM);
    cudaFuncSetAttribute(gemm_h<1, 1, 0, DM>, cudaFuncAttributeMaxDynamicSharedMemorySize, GEMM_SMEM);
    cudaFuncSetAttribute(gemm_h<1, 0, 1, FF>, cudaFuncAttributeMaxDynamicSharedMemorySize, GEMM_SMEM);
    cudaFuncSetAttribute(attn_h, cudaFuncAttributeMaxDynamicSharedMemorySize, ATTN_SMEM);

    // 0. fused convert of src + all weights to fp16 (one launch)
    cvt_all<<<(N4_ALL + 255) / 256, 256>>>(src, in_w, ow, w1, w2,
                                           src_h, win_h, wout_h, w1_h, w2_h);
    // 1. qkv = src @ in_w^T + b (fp16 out)
    gemm_h<1, 0, 0, DM><<<dim3(3 * DM / BN, T / BM), 128, GEMM_SMEM>>>(
        src_h, win_h, in_b, nullptr, qkv_h, T, 3 * DM);
    // 2. window-local attention -> ctx fp16
    attn_h<<<dim3(NH, NWIN, BB), 256, ATTN_SMEM>>>();
    // 3. x = ctx @ ow^T + ob + src (fp16 out, fp16 residual)
    gemm_h<1, 0, 1, DM><<<dim3(DM / BN, T / BM), 128, GEMM_SMEM>>>(
        ctx_h, wout_h, ob, src_h, x16, T, DM);
    // 4. h = LN(x)  (fp16 only)
    ln_h<<<T, 256>>>(x16, ln1g, ln1b, nullptr, h16);
    // 5. ff = relu(h @ w1^T + b1) (fp16 out)
    gemm_h<1, 1, 0, DM><<<dim3(FF / BN, T / BM), 128, GEMM_SMEM>>>(
        h16, w1_h, b1, nullptr, ff_h, T, FF);
    // 6. x = ff @ w2^T + b2 + h (fp16 out, fp16 residual)
    gemm_h<1, 0, 1, FF><<<dim3(DM / BN, T / BM), 128, GEMM_SMEM>>>(
        ff_h, w2_h, b2, h16, x16, T, DM);
    // 7. out = LN(x) (fp32)
    ln_h<<<T, 256>>>(x16, ln2g, ln2b, out, nullptr);
}

// round 10
// speedup vs baseline: 1.3515x; 1.2385x over previous
#include <cuda_runtime.h>
#include <cuda_fp16.h>
#include <cstdint>

// ---------------------------------------------------------------------------
// MultiAttnLayer, sm_103 baseline-ISA path. Round 10: MIO head-of-line fix —
// the per-kiter cp.async burst is spread across the ks-loop, interleaved with
// LDSM/HMMA, so LDSMs no longer queue behind a 1k-cycle LDGSTS burst.
// R9 fp16 dataflow otherwise unchanged.
// ---------------------------------------------------------------------------

constexpr int BB   = 4;
constexpr int SEQ  = 8192;
constexpr int DM   = 1024;
constexpr int NH   = 16;
constexpr int HD   = 64;
constexpr int WIN  = 128;
constexpr int NWIN = SEQ / WIN;
constexpr int FF   = 4096;
constexpr int T    = BB * SEQ;
constexpr float LN_EPS = 1e-5f;

// Scratch (device globals: allocation-free).
__device__ __half g_src_h[(size_t)T * DM];
__device__ __half g_win_h[3 * DM * DM];
__device__ __half g_wout_h[DM * DM];
__device__ __half g_w1_h[FF * DM];
__device__ __half g_w2_h[DM * FF];
__device__ __half g_qkv_h[(size_t)T * 3 * DM];
__device__ __half g_ctx_h[(size_t)T * DM];
__device__ __half g_h16[(size_t)T * DM];
__device__ __half g_ff_h[(size_t)T * FF];
__device__ __half g_x16[(size_t)T * DM];

// ========================= helpers =========================================
__device__ __forceinline__ uint32_t smem_u32(const void* p) {
    uint32_t a;
    asm("{ .reg .u64 t; cvta.to.shared.u64 t, %1; cvt.u32.u64 %0, t; }" : "=r"(a) : "l"(p));
    return a;
}
__device__ __forceinline__ void cp_async16(uint32_t dst, const void* src) {
    asm volatile("cp.async.cg.shared.global [%0], [%1], 16;" :: "r"(dst), "l"(src));
}
__device__ __forceinline__ void cp_commit() { asm volatile("cp.async.commit_group;"); }
template <int N> __device__ __forceinline__ void cp_wait() {
    asm volatile("cp.async.wait_group %0;" :: "n"(N));
}
#define LDSM_X4(r0, r1, r2, r3, addr)                                          \
    asm volatile("ldmatrix.sync.aligned.m8n8.x4.shared.b16 {%0,%1,%2,%3}, [%4];" \
        : "=r"(r0), "=r"(r1), "=r"(r2), "=r"(r3) : "r"(addr))
#define LDSM_X4_T(r0, r1, r2, r3, addr)                                        \
    asm volatile("ldmatrix.sync.aligned.m8n8.x4.trans.shared.b16 {%0,%1,%2,%3}, [%4];" \
        : "=r"(r0), "=r"(r1), "=r"(r2), "=r"(r3) : "r"(addr))

__device__ __forceinline__ void mma_f16(float c[4], const uint32_t a[4],
                                        uint32_t b0, uint32_t b1) {
    asm volatile(
        "mma.sync.aligned.m16n8k16.row.col.f32.f16.f16.f32 "
        "{%0,%1,%2,%3}, {%4,%5,%6,%7}, {%8,%9}, {%0,%1,%2,%3};\n"
        : "+f"(c[0]), "+f"(c[1]), "+f"(c[2]), "+f"(c[3])
        : "r"(a[0]), "r"(a[1]), "r"(a[2]), "r"(a[3]), "r"(b0), "r"(b1));
}

// ========================= fp16 GEMM =======================================
// C[M,N] = A[M,K] @ B[N,K]^T + bias[N] (+ fp16 residual).  A,B fp16; acc fp32.
// Tile 128x128, BK=64, 128 threads = 4 warps (2m x 2n, warp tile 64x64),
// 3-stage cp.async pipeline with issuance SPREAD across the ks-loop,
// 2 CTAs/SM, register double-buffered fragments.
constexpr int BM = 128, BN = 128, BK = 64, STAGES = 3;
constexpr int AROW = 144;                 // 64 halves + 8 pad
constexpr int A_ST = BM * AROW;           // 18432
constexpr int B_ST = BN * AROW;           // 18432
constexpr int ST   = A_ST + B_ST;         // 36864
constexpr int GEMM_SMEM = STAGES * ST;    // 110592

template <int OUT_HALF, int RELU, int RES, int KV>
__global__ __launch_bounds__(128, 2)
void gemm_h(const __half* __restrict__ A, const __half* __restrict__ B,
            const float* __restrict__ bias, const __half* __restrict__ Res,
            void* __restrict__ Cout, int M, int N)
{
    extern __shared__ char smraw[];
    const uint32_t sb = smem_u32(smraw);

    const int tid  = threadIdx.x;
    const int wid  = tid >> 5;
    const int lane = tid & 31;
    const int wm   = wid >> 1;           // 0..1
    const int wn   = wid & 1;            // 0..1
    const int bm   = blockIdx.y * BM;
    const int bn   = blockIdx.x * BN;
    constexpr int K = KV;

    float acc[4][8][4];
#pragma unroll
    for (int i = 0; i < 4; i++)
#pragma unroll
        for (int j = 0; j < 8; j++)
#pragma unroll
            for (int l = 0; l < 4; l++) acc[i][j][l] = 0.f;

    // Full-stage load (prologue only).
    auto load_stage = [&](int s, int k0) {
        const uint32_t ab = sb + s * ST;
#pragma unroll
        for (int i = 0; i < 8; i++) {
            int id = tid + i * 128;
            int r  = id >> 3;
            int c  = id & 7;
            cp_async16(ab + r * AROW + c * 16, A + (size_t)(bm + r) * K + k0 + c * 8);
        }
        const uint32_t bb = ab + A_ST;
#pragma unroll
        for (int i = 0; i < 8; i++) {
            int id = tid + i * 128;
            int r  = id >> 3;
            int c  = id & 7;
            cp_async16(bb + r * AROW + c * 16, B + (size_t)(bn + r) * K + k0 + c * 8);
        }
    };

    constexpr int NK = K / BK;
#pragma unroll
    for (int s = 0; s < STAGES - 1; s++) { load_stage(s, s * BK); cp_commit(); }

    const uint32_t a_lane = (uint32_t)((lane & 15) * AROW + (lane >> 4) * 16);
    const uint32_t b_lane = (uint32_t)(((lane & 7) + ((lane >> 4) & 1) * 8) * AROW +
                                       (((lane >> 3) & 1)) * 16);

    for (int k = 0; k < NK; k++) {
        cp_wait<STAGES - 2>();
        __syncthreads();

        // prefetch-target pointers (stage k+2)
        const bool     pf  = (k + STAGES - 1 < NK);
        const int      pk0 = (k + STAGES - 1) * BK;
        const uint32_t pab = sb + ((k + STAGES - 1) % STAGES) * ST;
        const uint32_t pbb = pab + A_ST;

        const uint32_t as = sb + (k % STAGES) * ST;
        const uint32_t a_base = as + wm * 64 * AROW + a_lane;
        const uint32_t b_base = as + A_ST + wn * 64 * AROW + b_lane;

        uint32_t a_f[2][4][4];
        uint32_t b_f[2][8][2];

        // prime ks=0 fragments
#pragma unroll
        for (int im = 0; im < 4; im++)
            LDSM_X4(a_f[0][im][0], a_f[0][im][1], a_f[0][im][2], a_f[0][im][3],
                    a_base + im * 16 * AROW);
#pragma unroll
        for (int p = 0; p < 4; p++) {
            uint32_t r0, r1, r2, r3;
            LDSM_X4(r0, r1, r2, r3, b_base + p * 16 * AROW);
            b_f[0][2 * p][0] = r0; b_f[0][2 * p][1] = r1;
            b_f[0][2 * p + 1][0] = r2; b_f[0][2 * p + 1][1] = r3;
        }

#pragma unroll
        for (int ks = 0; ks < 4; ks++) {
            const int cb = ks & 1;
            const int nb = cb ^ 1;

            // Spread prefetch: 2 A-chunks + 2 B-chunks of stage k+2 per ks.
            if (pf) {
#pragma unroll
                for (int j = 0; j < 2; j++) {
                    int id = tid + (2 * ks + j) * 128;
                    int r  = id >> 3;
                    int c  = id & 7;
                    cp_async16(pab + r * AROW + c * 16,
                               A + (size_t)(bm + r) * K + pk0 + c * 8);
                }
#pragma unroll
                for (int j = 0; j < 2; j++) {
                    int id = tid + (2 * ks + j) * 128;
                    int r  = id >> 3;
                    int c  = id & 7;
                    cp_async16(pbb + r * AROW + c * 16,
                               B + (size_t)(bn + r) * K + pk0 + c * 8);
                }
            }

            if (ks < 3) {
#pragma unroll
                for (int im = 0; im < 4; im++)
                    LDSM_X4(a_f[nb][im][0], a_f[nb][im][1], a_f[nb][im][2], a_f[nb][im][3],
                            a_base + im * 16 * AROW + (ks + 1) * 32);
#pragma unroll
                for (int p = 0; p < 4; p++) {
                    uint32_t r0, r1, r2, r3;
                    LDSM_X4(r0, r1, r2, r3, b_base + p * 16 * AROW + (ks + 1) * 32);
                    b_f[nb][2 * p][0] = r0; b_f[nb][2 * p][1] = r1;
                    b_f[nb][2 * p + 1][0] = r2; b_f[nb][2 * p + 1][1] = r3;
                }
            }
#pragma unroll
            for (int im = 0; im < 4; im++)
#pragma unroll
                for (int n = 0; n < 8; n++)
                    mma_f16(acc[im][n], a_f[cb][im], b_f[cb][n][0], b_f[cb][n][1]);
        }
        cp_commit();
    }

    // Epilogue (fp16 residual, optional fp16/fp32 output)
#pragma unroll
    for (int im = 0; im < 4; im++) {
        const int row = bm + wm * 64 + im * 16 + (lane >> 2);
#pragma unroll
        for (int n = 0; n < 8; n++) {
            const int col = bn + wn * 64 + n * 8 + (lane & 3) * 2;
            const float2 bv = *(const float2*)(bias + col);
            float v00 = acc[im][n][0] + bv.x, v01 = acc[im][n][1] + bv.y;
            float v10 = acc[im][n][2] + bv.x, v11 = acc[im][n][3] + bv.y;
            if (RES) {
                const float2 r0 = __half22float2(
                    *(const __half2*)(Res + (size_t)row * N + col));
                const float2 r1 = __half22float2(
                    *(const __half2*)(Res + (size_t)(row + 8) * N + col));
                v00 += r0.x; v01 += r0.y;
                v10 += r1.x; v11 += r1.y;
            }
            if (RELU) {
                v00 = fmaxf(v00, 0.f); v01 = fmaxf(v01, 0.f);
                v10 = fmaxf(v10, 0.f); v11 = fmaxf(v11, 0.f);
            }
            if (OUT_HALF) {
                __half2* C = (__half2*)Cout;
                C[((size_t)row * N + col) >> 1]       = __floats2half2_rn(v00, v01);
                C[((size_t)(row + 8) * N + col) >> 1] = __floats2half2_rn(v10, v11);
            } else {
                float* C = (float*)Cout;
                *(float2*)(C + (size_t)row * N + col)       = make_float2(v00, v01);
                *(float2*)(C + (size_t)(row + 8) * N + col) = make_float2(v10, v11);
            }
        }
    }
}

// ===================== window-local attention (fp16) =======================
constexpr int QKV_B  = 128 * 144;
constexpr int P_ROWB = 272;
constexpr int OFF_P  = 3 * QKV_B;
constexpr int ATTN_SMEM = OFF_P + 128 * P_ROWB;   // 90112

__global__ __launch_bounds__(256, 2)
void attn_h()
{
    extern __shared__ char smraw[];
    const uint32_t sb = smem_u32(smraw);
    const uint32_t qh = sb;
    const uint32_t kh = sb + QKV_B;
    const uint32_t vh = sb + 2 * QKV_B;

    const int h  = blockIdx.x;
    const int w  = blockIdx.y;
    const int b  = blockIdx.z;
    const int t0 = b * SEQ + w * WIN;

    const int tid  = threadIdx.x;
    const int wid  = tid >> 5;
    const int lane = tid & 31;
    const int gid  = lane >> 2;
    const int tig  = lane & 3;

#pragma unroll
    for (int i = 0; i < 4; i++) {
        int id = tid + i * 256;
        int r  = id >> 3;
        int c  = id & 7;
        const __half* base = g_qkv_h + (size_t)(t0 + r) * (3 * DM) + h * HD + c * 8;
        uint32_t doff = r * 144 + c * 16;
        cp_async16(qh + doff, base);
        cp_async16(kh + doff, base + DM);
        cp_async16(vh + doff, base + 2 * DM);
    }
    cp_commit();
    cp_wait<0>();
    __syncthreads();

    const int m0 = wid * 16;

    // ---- scores = Q @ K^T ----
    float sc[16][4];
#pragma unroll
    for (int n = 0; n < 16; n++)
#pragma unroll
        for (int l = 0; l < 4; l++) sc[n][l] = 0.f;

    const uint32_t a_base = qh + (m0 + (lane & 15)) * 144 + (lane >> 4) * 16;
    const uint32_t k_base = kh + ((lane & 7) + ((lane >> 4) & 1) * 8) * 144 +
                            ((lane >> 3) & 1) * 16;
#pragma unroll
    for (int ks = 0; ks < 4; ks++) {
        uint32_t a[4];
        LDSM_X4(a[0], a[1], a[2], a[3], a_base + ks * 32);
#pragma unroll
        for (int p = 0; p < 8; p++) {
            uint32_t r0, r1, r2, r3;
            LDSM_X4(r0, r1, r2, r3, k_base + p * 16 * 144 + ks * 32);
            mma_f16(sc[2 * p], a, r0, r1);
            mma_f16(sc[2 * p + 1], a, r2, r3);
        }
    }

    // ---- softmax in registers ----
    const float scale = 0.125f;
    float mA = -1e30f, mB = -1e30f;
#pragma unroll
    for (int n = 0; n < 16; n++) {
#pragma unroll
        for (int l = 0; l < 4; l++) sc[n][l] *= scale;
        mA = fmaxf(mA, fmaxf(sc[n][0], sc[n][1]));
        mB = fmaxf(mB, fmaxf(sc[n][2], sc[n][3]));
    }
    mA = fmaxf(mA, __shfl_xor_sync(0xffffffffu, mA, 1));
    mA = fmaxf(mA, __shfl_xor_sync(0xffffffffu, mA, 2));
    mB = fmaxf(mB, __shfl_xor_sync(0xffffffffu, mB, 1));
    mB = fmaxf(mB, __shfl_xor_sync(0xffffffffu, mB, 2));

    float sA = 0.f, sB = 0.f;
#pragma unroll
    for (int n = 0; n < 16; n++) {
        sc[n][0] = __expf(sc[n][0] - mA);
        sc[n][1] = __expf(sc[n][1] - mA);
        sc[n][2] = __expf(sc[n][2] - mB);
        sc[n][3] = __expf(sc[n][3] - mB);
        sA += sc[n][0] + sc[n][1];
        sB += sc[n][2] + sc[n][3];
    }
    sA += __shfl_xor_sync(0xffffffffu, sA, 1);
    sA += __shfl_xor_sync(0xffffffffu, sA, 2);
    sB += __shfl_xor_sync(0xffffffffu, sB, 1);
    sB += __shfl_xor_sync(0xffffffffu, sB, 2);
    const float invA = 1.f / sA, invB = 1.f / sB;

    {
        const int rA = m0 + gid;
        __half2* pA = (__half2*)(smraw + OFF_P + rA * P_ROWB);
        __half2* pB = (__half2*)(smraw + OFF_P + (rA + 8) * P_ROWB);
#pragma unroll
        for (int n = 0; n < 16; n++) {
            const int c2 = (n * 8 + tig * 2) >> 1;
            pA[c2] = __floats2half2_rn(sc[n][0] * invA, sc[n][1] * invA);
            pB[c2] = __floats2half2_rn(sc[n][2] * invB, sc[n][3] * invB);
        }
    }
    __syncthreads();

    // ---- ctx = P @ V ----
    float o[8][4];
#pragma unroll
    for (int n = 0; n < 8; n++)
#pragma unroll
        for (int l = 0; l < 4; l++) o[n][l] = 0.f;

    const uint32_t p_base = sb + OFF_P + (m0 + (lane & 15)) * P_ROWB + (lane >> 4) * 16;
    const uint32_t v_base = vh + ((lane & 7) + ((lane >> 3) & 1) * 8) * 144 +
                            (lane >> 4) * 16;
#pragma unroll
    for (int ks = 0; ks < 8; ks++) {
        uint32_t a[4];
        LDSM_X4(a[0], a[1], a[2], a[3], p_base + ks * 32);
#pragma unroll
        for (int p = 0; p < 4; p++) {
            uint32_t r0, r1, r2, r3;
            LDSM_X4_T(r0, r1, r2, r3, v_base + ks * 16 * 144 + p * 32);
            mma_f16(o[2 * p], a, r0, r1);
            mma_f16(o[2 * p + 1], a, r2, r3);
        }
    }

    {
        const int r = m0 + gid;
#pragma unroll
        for (int n = 0; n < 8; n++) {
            const int c = h * HD + n * 8 + tig * 2;
            __half2* o0 = (__half2*)(g_ctx_h + (size_t)(t0 + r) * DM + c);
            __half2* o1 = (__half2*)(g_ctx_h + (size_t)(t0 + r + 8) * DM + c);
            *o0 = __floats2half2_rn(o[n][0], o[n][1]);
            *o1 = __floats2half2_rn(o[n][2], o[n][3]);
        }
    }
}

// ===================== LayerNorm (fp16 in, fp32/fp16 out) ==================
__global__ __launch_bounds__(256)
void ln_h(const __half* __restrict__ X,
          const float* __restrict__ gam, const float* __restrict__ bet,
          float* __restrict__ out32, __half* __restrict__ out16)
{
    const int t    = blockIdx.x;
    const int tid  = threadIdx.x;
    const int lane = tid & 31;
    const int wid  = tid >> 5;

    const size_t base = (size_t)t * DM + tid * 4;
    float2 a0 = __half22float2(*(const __half2*)(X + base));
    float2 a1 = __half22float2(*(const __half2*)(X + base + 2));
    float x0 = a0.x, x1 = a0.y, x2 = a1.x, x3 = a1.y;

    float s = x0 + x1 + x2 + x3;
    float q = x0 * x0 + x1 * x1 + x2 * x2 + x3 * x3;
#pragma unroll
    for (int o = 16; o > 0; o >>= 1) {
        s += __shfl_xor_sync(0xffffffffu, s, o);
        q += __shfl_xor_sync(0xffffffffu, q, o);
    }
    __shared__ float rs[8], rq[8];
    if (lane == 0) { rs[wid] = s; rq[wid] = q; }
    __syncthreads();
    if (wid == 0) {
        s = (lane < 8) ? rs[lane] : 0.f;
        q = (lane < 8) ? rq[lane] : 0.f;
#pragma unroll
        for (int o = 4; o > 0; o >>= 1) {
            s += __shfl_xor_sync(0xffffffffu, s, o);
            q += __shfl_xor_sync(0xffffffffu, q, o);
        }
        if (lane == 0) { rs[0] = s; rq[0] = q; }
    }
    __syncthreads();
    const float mu   = rs[0] * (1.f / DM);
    const float var  = rq[0] * (1.f / DM) - mu * mu;
    const float rstd = rsqrtf(var + LN_EPS);

    float4 gv = *(const float4*)(gam + tid * 4);
    float4 bv = *(const float4*)(bet + tid * 4);
    float r0 = (x0 - mu) * rstd * gv.x + bv.x;
    float r1 = (x1 - mu) * rstd * gv.y + bv.y;
    float r2 = (x2 - mu) * rstd * gv.z + bv.z;
    float r3 = (x3 - mu) * rstd * gv.w + bv.w;
    if (out32) {
        float4 r;
        r.x = r0; r.y = r1; r.z = r2; r.w = r3;
        *(float4*)(out32 + base) = r;
    }
    if (out16) {
        *(__half2*)(out16 + base)     = __floats2half2_rn(r0, r1);
        *(__half2*)(out16 + base + 2) = __floats2half2_rn(r2, r3);
    }
}

// ================= fused fp32 -> fp16 convert (all 5 arrays) ===============
constexpr int N4_SRC = T * DM / 4;
constexpr int N4_WIN = 3 * DM * DM / 4;
constexpr int N4_WO  = DM * DM / 4;
constexpr int N4_W1  = FF * DM / 4;
constexpr int N4_W2  = DM * FF / 4;
constexpr int N4_ALL = N4_SRC + N4_WIN + N4_WO + N4_W1 + N4_W2;

__global__ __launch_bounds__(256)
void cvt_all(const float* __restrict__ s0, const float* __restrict__ s1,
             const float* __restrict__ s2, const float* __restrict__ s3,
             const float* __restrict__ s4,
             __half* __restrict__ d0, __half* __restrict__ d1,
             __half* __restrict__ d2, __half* __restrict__ d3,
             __half* __restrict__ d4)
{
    int i = blockIdx.x * 256 + threadIdx.x;
    const float* in;
    __half* out;
    if (i < N4_SRC)                       { in = s0; out = d0; }
    else if ((i -= N4_SRC) < N4_WIN)      { in = s1; out = d1; }
    else if ((i -= N4_WIN) < N4_WO)       { in = s2; out = d2; }
    else if ((i -= N4_WO)  < N4_W1)       { in = s3; out = d3; }
    else if ((i -= N4_W1)  < N4_W2)       { in = s4; out = d4; }
    else return;
    float4 v = *(const float4*)(in + (size_t)i * 4);
    *(__half2*)(out + (size_t)i * 4)     = __floats2half2_rn(v.x, v.y);
    *(__half2*)(out + (size_t)i * 4 + 2) = __floats2half2_rn(v.z, v.w);
}

// ---------------------------------------------------------------------------
extern "C" void kernel_launch(void* const* d_in, const int* in_sizes, int n_in,
                              void* d_out, int out_size)
{
    const float* src   = (const float*)d_in[0];
    const float* in_w  = (const float*)d_in[1];
    const float* in_b  = (const float*)d_in[2];
    const float* ow    = (const float*)d_in[3];
    const float* ob    = (const float*)d_in[4];
    const float* w1    = (const float*)d_in[5];
    const float* b1    = (const float*)d_in[6];
    const float* w2    = (const float*)d_in[7];
    const float* b2    = (const float*)d_in[8];
    const float* ln1g  = (const float*)d_in[9];
    const float* ln1b  = (const float*)d_in[10];
    const float* ln2g  = (const float*)d_in[11];
    const float* ln2b  = (const float*)d_in[12];
    float* out = (float*)d_out;

    __half *src_h, *win_h, *wout_h, *w1_h, *w2_h, *qkv_h, *ctx_h, *h16, *ff_h, *x16;
    cudaGetSymbolAddress((void**)&src_h,  g_src_h);
    cudaGetSymbolAddress((void**)&win_h,  g_win_h);
    cudaGetSymbolAddress((void**)&wout_h, g_wout_h);
    cudaGetSymbolAddress((void**)&w1_h,   g_w1_h);
    cudaGetSymbolAddress((void**)&w2_h,   g_w2_h);
    cudaGetSymbolAddress((void**)&qkv_h,  g_qkv_h);
    cudaGetSymbolAddress((void**)&ctx_h,  g_ctx_h);
    cudaGetSymbolAddress((void**)&h16,    g_h16);
    cudaGetSymbolAddress((void**)&ff_h,   g_ff_h);
    cudaGetSymbolAddress((void**)&x16,    g_x16);

    cudaFuncSetAttribute(gemm_h<1, 0, 0, DM>, cudaFuncAttributeMaxDynamicSharedMemorySize, GEMM_SMEM);
    cudaFuncSetAttribute(gemm_h<1, 0, 1, DM>, cudaFuncAttributeMaxDynamicSharedMemorySize, GEMM_SMEM);
    cudaFuncSetAttribute(gemm_h<1, 1, 0, DM>, cudaFuncAttributeMaxDynamicSharedMemorySize, GEMM_SMEM);
    cudaFuncSetAttribute(gemm_h<1, 0, 1, FF>, cudaFuncAttributeMaxDynamicSharedMemorySize, GEMM_SMEM);
    cudaFuncSetAttribute(attn_h, cudaFuncAttributeMaxDynamicSharedMemorySize, ATTN_SMEM);

    // 0. fused convert of src + all weights to fp16 (one launch)
    cvt_all<<<(N4_ALL + 255) / 256, 256>>>(src, in_w, ow, w1, w2,
                                           src_h, win_h, wout_h, w1_h, w2_h);
    // 1. qkv = src @ in_w^T + b (fp16 out)
    gemm_h<1, 0, 0, DM><<<dim3(3 * DM / BN, T / BM), 128, GEMM_SMEM>>>(
        src_h, win_h, in_b, nullptr, qkv_h, T, 3 * DM);
    // 2. window-local attention -> ctx fp16
    attn_h<<<dim3(NH, NWIN, BB), 256, ATTN_SMEM>>>();
    // 3. x = ctx @ ow^T + ob + src (fp16 out, fp16 residual)
    gemm_h<1, 0, 1, DM><<<dim3(DM / BN, T / BM), 128, GEMM_SMEM>>>(
        ctx_h, wout_h, ob, src_h, x16, T, DM);
    // 4. h = LN(x)  (fp16 only)
    ln_h<<<T, 256>>>(x16, ln1g, ln1b, nullptr, h16);
    // 5. ff = relu(h @ w1^T + b1) (fp16 out)
    gemm_h<1, 1, 0, DM><<<dim3(FF / BN, T / BM), 128, GEMM_SMEM>>>(
        h16, w1_h, b1, nullptr, ff_h, T, FF);
    // 6. x = ff @ w2^T + b2 + h (fp16 out, fp16 residual)
    gemm_h<1, 0, 1, FF><<<dim3(DM / BN, T / BM), 128, GEMM_SMEM>>>(
        ff_h, w2_h, b2, h16, x16, T, DM);
    // 7. out = LN(x) (fp32)
    ln_h<<<T, 256>>>(x16, ln2g, ln2b, out, nullptr);
}